// round 3
// baseline (speedup 1.0000x reference)
#include <cuda_runtime.h>

#define SEQ 4096
#define EMB 1024
#define NH  16
#define HD  64
#define QKVN (3*EMB)

typedef unsigned long long u64;

__device__ __forceinline__ u64 pack2(float lo, float hi) {
    u64 r; asm("mov.b64 %0, {%1, %2};" : "=l"(r) : "f"(lo), "f"(hi)); return r;
}
__device__ __forceinline__ u64 ffma2(u64 a, u64 b, u64 c) {
    u64 d; asm("fma.rn.f32x2 %0, %1, %2, %3;" : "=l"(d) : "l"(a), "l"(b), "l"(c)); return d;
}
__device__ __forceinline__ u64 fmul2(u64 a, u64 b) {
    u64 d; asm("mul.rn.f32x2 %0, %1, %2;" : "=l"(d) : "l"(a), "l"(b)); return d;
}
__device__ __forceinline__ float2 unpack2(u64 v) {
    float2 f; asm("mov.b64 {%0, %1}, %2;" : "=f"(f.x), "=f"(f.y) : "l"(v)); return f;
}

union F8 {
    float4 v4[2];
    u64    u[4];
    float  f[8];
};

// Scratch (no cudaMalloc allowed)
__device__ float g_qkv[(size_t)SEQ * QKVN];
__device__ float g_att[(size_t)SEQ * EMB];

// ---------------------------------------------------------------------------
// SGEMM: C[M,N] = A[M,K] @ B[N,K]^T + bias[N]
// 128x128 tile, BK=16, 256 threads, 8x8 micro-tile, FFMA2 inner loop.
// ---------------------------------------------------------------------------
__global__ __launch_bounds__(256, 2)
void sgemm_bias(const float* __restrict__ A, const float* __restrict__ B,
                const float* __restrict__ bias, float* __restrict__ C,
                int M, int N, int K)
{
    const int BK = 16;
    __shared__ float As[16][132];
    __shared__ float Bs[16][132];

    int t  = threadIdx.x;
    int tx = t & 15;
    int ty = t >> 4;
    int bm = blockIdx.y * 128;
    int bn = blockIdx.x * 128;

    const float* Ab = A + (size_t)bm * K;
    const float* Bb = B + (size_t)bn * K;

    int lm = t >> 2;
    int lk = (t & 3) << 2;

    u64 acc2[8][4];
#pragma unroll
    for (int i = 0; i < 8; i++)
#pragma unroll
        for (int j = 0; j < 4; j++) acc2[i][j] = 0ull;

    for (int k0 = 0; k0 < K; k0 += BK) {
#pragma unroll
        for (int p = 0; p < 2; p++) {
            int m = lm + p * 64;
            float4 va = *(const float4*)(Ab + (size_t)m * K + k0 + lk);
            As[lk + 0][m] = va.x; As[lk + 1][m] = va.y;
            As[lk + 2][m] = va.z; As[lk + 3][m] = va.w;
            float4 vb = *(const float4*)(Bb + (size_t)m * K + k0 + lk);
            Bs[lk + 0][m] = vb.x; Bs[lk + 1][m] = vb.y;
            Bs[lk + 2][m] = vb.z; Bs[lk + 3][m] = vb.w;
        }
        __syncthreads();

#pragma unroll
        for (int k = 0; k < BK; k++) {
            F8 Au, Bu;
            Au.v4[0] = *(const float4*)&As[k][ty * 8];
            Au.v4[1] = *(const float4*)&As[k][ty * 8 + 4];
            Bu.v4[0] = *(const float4*)&Bs[k][tx * 8];
            Bu.v4[1] = *(const float4*)&Bs[k][tx * 8 + 4];
            u64 ap[8];
#pragma unroll
            for (int i = 0; i < 8; i++) ap[i] = pack2(Au.f[i], Au.f[i]);
#pragma unroll
            for (int i = 0; i < 8; i++)
#pragma unroll
                for (int j = 0; j < 4; j++)
                    acc2[i][j] = ffma2(ap[i], Bu.u[j], acc2[i][j]);
        }
        __syncthreads();
    }

#pragma unroll
    for (int i = 0; i < 8; i++) {
        int m = bm + ty * 8 + i;
        float* Crow = C + (size_t)m * N + bn + tx * 8;
        const float* brow = bias + bn + tx * 8;
#pragma unroll
        for (int j = 0; j < 2; j++) {
            float2 p0 = unpack2(acc2[i][j * 2 + 0]);
            float2 p1 = unpack2(acc2[i][j * 2 + 1]);
            float4 v;
            v.x = p0.x + brow[j * 4 + 0];
            v.y = p0.y + brow[j * 4 + 1];
            v.z = p1.x + brow[j * 4 + 2];
            v.w = p1.y + brow[j * 4 + 3];
            *(float4*)(Crow + j * 4) = v;
        }
    }
}

// ---------------------------------------------------------------------------
// Flash attention, GEMM-structured, FFMA2 inner loops.
// CTA: 128 query rows x 1 head. 256 threads as 16x16.
// smem: Q^T[64][132], K^T[64][132], V[128][68], P[128][132]  (~166 KB)
// ---------------------------------------------------------------------------
#define BQ 128
#define BKEY 128

__global__ __launch_bounds__(256)
void attn_kernel()
{
    extern __shared__ float sm[];
    float* Qs = sm;
    float* Ks = Qs + 64 * 132;
    float* Vs = Ks + 64 * 132;
    float* Ps = Vs + 128 * 68;

    int h  = blockIdx.y;
    int q0 = blockIdx.x * BQ;
    int t  = threadIdx.x;
    int tx = t & 15;
    int ty = t >> 4;

    // ---- load Q tile transposed into smem, scale folded in ----
    {
        int row = t >> 1;
        int dbase = (t & 1) * 32;
        const float* src = g_qkv + (size_t)(q0 + row) * QKVN + h * 192 + dbase;
#pragma unroll
        for (int c = 0; c < 8; c++) {
            float4 v = *(const float4*)(src + c * 4);
            int d = dbase + c * 4;
            Qs[(d + 0) * 132 + row] = v.x * 0.125f;
            Qs[(d + 1) * 132 + row] = v.y * 0.125f;
            Qs[(d + 2) * 132 + row] = v.z * 0.125f;
            Qs[(d + 3) * 132 + row] = v.w * 0.125f;
        }
    }

    float m_run[8], l_run[8];
    u64 o2[8][2];
#pragma unroll
    for (int i = 0; i < 8; i++) {
        m_run[i] = -1e30f;
        l_run[i] = 0.f;
        o2[i][0] = 0ull; o2[i][1] = 0ull;
    }

    for (int kt = 0; kt < SEQ; kt += BKEY) {
        __syncthreads();

        // ---- load K (transposed) and V (k-major) ----
        {
            int row = t >> 1;
            int dbase = (t & 1) * 32;
            const float* kp = g_qkv + (size_t)(kt + row) * QKVN + h * 192 + 64 + dbase;
#pragma unroll
            for (int c = 0; c < 8; c++) {
                float4 v = *(const float4*)(kp + c * 4);
                int d = dbase + c * 4;
                Ks[(d + 0) * 132 + row] = v.x;
                Ks[(d + 1) * 132 + row] = v.y;
                Ks[(d + 2) * 132 + row] = v.z;
                Ks[(d + 3) * 132 + row] = v.w;
            }
            const float* vp = g_qkv + (size_t)(kt + row) * QKVN + h * 192 + 128 + dbase;
#pragma unroll
            for (int c = 0; c < 8; c++)
                *(float4*)&Vs[row * 68 + dbase + c * 4] = *(const float4*)(vp + c * 4);
        }
        __syncthreads();

        // ---- logits: Q_tile @ K_tile^T via FFMA2 ----
        u64 acc2[8][4];
#pragma unroll
        for (int i = 0; i < 8; i++)
#pragma unroll
            for (int j = 0; j < 4; j++) acc2[i][j] = 0ull;

#pragma unroll 4
        for (int k = 0; k < HD; k++) {
            F8 Au, Bu;
            Au.v4[0] = *(const float4*)&Qs[k * 132 + ty * 8];
            Au.v4[1] = *(const float4*)&Qs[k * 132 + ty * 8 + 4];
            Bu.v4[0] = *(const float4*)&Ks[k * 132 + tx * 8];
            Bu.v4[1] = *(const float4*)&Ks[k * 132 + tx * 8 + 4];
            u64 ap[8];
#pragma unroll
            for (int i = 0; i < 8; i++) ap[i] = pack2(Au.f[i], Au.f[i]);
#pragma unroll
            for (int i = 0; i < 8; i++)
#pragma unroll
                for (int j = 0; j < 4; j++)
                    acc2[i][j] = ffma2(ap[i], Bu.u[j], acc2[i][j]);
        }

        // ---- online softmax ----
#pragma unroll
        for (int i = 0; i < 8; i++) {
            float a[8];
#pragma unroll
            for (int j = 0; j < 4; j++) {
                float2 p = unpack2(acc2[i][j]);
                a[j * 2] = p.x; a[j * 2 + 1] = p.y;
            }
            float tm = a[0];
#pragma unroll
            for (int j = 1; j < 8; j++) tm = fmaxf(tm, a[j]);
            tm = fmaxf(tm, __shfl_xor_sync(0xffffffffu, tm, 1));
            tm = fmaxf(tm, __shfl_xor_sync(0xffffffffu, tm, 2));
            tm = fmaxf(tm, __shfl_xor_sync(0xffffffffu, tm, 4));
            tm = fmaxf(tm, __shfl_xor_sync(0xffffffffu, tm, 8));

            float mn = fmaxf(m_run[i], tm);
            float corr = __expf(m_run[i] - mn);
            m_run[i] = mn;
            l_run[i] *= corr;
            u64 c2 = pack2(corr, corr);
            o2[i][0] = fmul2(o2[i][0], c2);
            o2[i][1] = fmul2(o2[i][1], c2);

            float s = 0.f;
#pragma unroll
            for (int j = 0; j < 8; j++) {
                float p = __expf(a[j] - mn);
                s += p;
                a[j] = p;
            }
            s += __shfl_xor_sync(0xffffffffu, s, 1);
            s += __shfl_xor_sync(0xffffffffu, s, 2);
            s += __shfl_xor_sync(0xffffffffu, s, 4);
            s += __shfl_xor_sync(0xffffffffu, s, 8);
            l_run[i] += s;

            *(float4*)&Ps[(ty * 8 + i) * 132 + tx * 8]     = *(float4*)&a[0];
            *(float4*)&Ps[(ty * 8 + i) * 132 + tx * 8 + 4] = *(float4*)&a[4];
        }
        __syncthreads();

        // ---- PV via FFMA2: o2[i][:] += P[row][k] * V[k][tx*4..tx*4+3] ----
#pragma unroll 2
        for (int k = 0; k < BKEY; k += 4) {
            F8 V0, V1;
            V0.v4[0] = *(const float4*)&Vs[(k + 0) * 68 + tx * 4];
            V0.v4[1] = *(const float4*)&Vs[(k + 1) * 68 + tx * 4];
            V1.v4[0] = *(const float4*)&Vs[(k + 2) * 68 + tx * 4];
            V1.v4[1] = *(const float4*)&Vs[(k + 3) * 68 + tx * 4];
#pragma unroll
            for (int i = 0; i < 8; i++) {
                float4 p4 = *(const float4*)&Ps[(ty * 8 + i) * 132 + k];
                u64 px = pack2(p4.x, p4.x);
                u64 py = pack2(p4.y, p4.y);
                u64 pz = pack2(p4.z, p4.z);
                u64 pw = pack2(p4.w, p4.w);
                o2[i][0] = ffma2(px, V0.u[0], o2[i][0]);
                o2[i][1] = ffma2(px, V0.u[1], o2[i][1]);
                o2[i][0] = ffma2(py, V0.u[2], o2[i][0]);
                o2[i][1] = ffma2(py, V0.u[3], o2[i][1]);
                o2[i][0] = ffma2(pz, V1.u[0], o2[i][0]);
                o2[i][1] = ffma2(pz, V1.u[1], o2[i][1]);
                o2[i][0] = ffma2(pw, V1.u[2], o2[i][0]);
                o2[i][1] = ffma2(pw, V1.u[3], o2[i][1]);
            }
        }
    }

    // ---- normalize and write ----
#pragma unroll
    for (int i = 0; i < 8; i++) {
        float inv = 1.f / l_run[i];
        float2 a0 = unpack2(o2[i][0]);
        float2 a1 = unpack2(o2[i][1]);
        float4 v;
        v.x = a0.x * inv; v.y = a0.y * inv;
        v.z = a1.x * inv; v.w = a1.y * inv;
        *(float4*)(g_att + (size_t)(q0 + ty * 8 + i) * EMB + h * HD + tx * 4) = v;
    }
}

static const int ATTN_SMEM = (64 * 132 + 64 * 132 + 128 * 68 + 128 * 132) * (int)sizeof(float);

extern "C" void kernel_launch(void* const* d_in, const int* in_sizes, int n_in,
                              void* d_out, int out_size)
{
    (void)in_sizes; (void)n_in; (void)out_size;
    const float* x    = (const float*)d_in[0];
    const float* Wqkv = (const float*)d_in[1];
    const float* bqkv = (const float*)d_in[2];
    const float* Wo   = (const float*)d_in[3];
    const float* bo   = (const float*)d_in[4];
    float* out = (float*)d_out;

    float *qkv, *att;
    cudaGetSymbolAddress((void**)&qkv, g_qkv);
    cudaGetSymbolAddress((void**)&att, g_att);

    cudaFuncSetAttribute(attn_kernel,
                         cudaFuncAttributeMaxDynamicSharedMemorySize, ATTN_SMEM);

    dim3 g1(QKVN / 128, SEQ / 128);
    sgemm_bias<<<g1, 256>>>(x, Wqkv, bqkv, qkv, SEQ, QKVN, EMB);

    dim3 g2(SEQ / BQ, NH);
    attn_kernel<<<g2, 256, ATTN_SMEM>>>();

    dim3 g3(EMB / 128, SEQ / 128);
    sgemm_bias<<<g3, 256>>>(att, Wo, bo, out, SEQ, EMB, EMB);
}

// round 5
// speedup vs baseline: 2.8333x; 2.8333x over previous
#include <cuda_runtime.h>
#include <cuda_bf16.h>
#include <cstdint>

#define SEQ 4096
#define EMB 1024
#define NH  16
#define HD  64
#define QKVN (3*EMB)

typedef uint32_t u32;

// ---------------- scratch (no cudaMalloc allowed) ----------------
__device__ __nv_bfloat16 g_x_hi[(size_t)SEQ * EMB];
__device__ __nv_bfloat16 g_x_lo[(size_t)SEQ * EMB];
__device__ __nv_bfloat16 g_wqkv_hi[(size_t)QKVN * EMB];
__device__ __nv_bfloat16 g_wqkv_lo[(size_t)QKVN * EMB];
__device__ __nv_bfloat16 g_wo_hi[(size_t)EMB * EMB];
__device__ __nv_bfloat16 g_wo_lo[(size_t)EMB * EMB];
__device__ __nv_bfloat16 g_qkv_hi[(size_t)SEQ * QKVN];
__device__ __nv_bfloat16 g_qkv_lo[(size_t)SEQ * QKVN];
__device__ __nv_bfloat16 g_att_hi[(size_t)SEQ * EMB];
__device__ __nv_bfloat16 g_att_lo[(size_t)SEQ * EMB];

// ---------------- helpers ----------------
__device__ __forceinline__ u32 smem_u32(const void* p) {
    u32 a;
    asm("{ .reg .u64 t; cvta.to.shared.u64 t, %1; cvt.u32.u64 %0, t; }" : "=r"(a) : "l"(p));
    return a;
}
__device__ __forceinline__ void ldm_x4(u32 r[4], u32 a) {
    asm volatile("ldmatrix.sync.aligned.m8n8.x4.shared.b16 {%0,%1,%2,%3}, [%4];"
                 : "=r"(r[0]), "=r"(r[1]), "=r"(r[2]), "=r"(r[3]) : "r"(a));
}
__device__ __forceinline__ void ldm_x4_t(u32 r[4], u32 a) {
    asm volatile("ldmatrix.sync.aligned.m8n8.x4.trans.shared.b16 {%0,%1,%2,%3}, [%4];"
                 : "=r"(r[0]), "=r"(r[1]), "=r"(r[2]), "=r"(r[3]) : "r"(a));
}
__device__ __forceinline__ void mma_bf16(float c[4], const u32 a[4], u32 b0, u32 b1) {
    asm volatile("mma.sync.aligned.m16n8k16.row.col.f32.bf16.bf16.f32 "
                 "{%0,%1,%2,%3}, {%4,%5,%6,%7}, {%8,%9}, {%0,%1,%2,%3};"
                 : "+f"(c[0]), "+f"(c[1]), "+f"(c[2]), "+f"(c[3])
                 : "r"(a[0]), "r"(a[1]), "r"(a[2]), "r"(a[3]), "r"(b0), "r"(b1));
}
__device__ __forceinline__ void split_pair(float v0, float v1,
                                           __nv_bfloat162& h, __nv_bfloat162& l) {
    h = __floats2bfloat162_rn(v0, v1);
    l = __floats2bfloat162_rn(v0 - __bfloat162float(h.x), v1 - __bfloat162float(h.y));
}

// ---------------- fp32 -> bf16 hi/lo split ----------------
__global__ void split_kernel(const float* __restrict__ src,
                             __nv_bfloat16* __restrict__ hi,
                             __nv_bfloat16* __restrict__ lo, int n4)
{
    int i = blockIdx.x * blockDim.x + threadIdx.x;
    if (i >= n4) return;
    float4 v = *(const float4*)(src + (size_t)i * 4);
    __nv_bfloat162 h0, l0, h1, l1;
    split_pair(v.x, v.y, h0, l0);
    split_pair(v.z, v.w, h1, l1);
    __nv_bfloat162 hh[2] = {h0, h1}, ll[2] = {l0, l1};
    *(uint2*)(hi + (size_t)i * 4) = *(uint2*)hh;
    *(uint2*)(lo + (size_t)i * 4) = *(uint2*)ll;
}

// ---------------------------------------------------------------------------
// Linear GEMM via mma.sync bf16 3-term split.
// C[M,N] = A[M,K] @ B[N,K]^T + bias.  128x128 tile, 8 warps (4m x 2n), BK=64.
// splitout: 0 -> f32 out (Cf), 1 -> bf16 hi/lo out (Chi/Clo).
// ---------------------------------------------------------------------------
#define LIN_SMEM (4 * 128 * 72 * 2)

__global__ __launch_bounds__(256, 2)
void lin_mma(const __nv_bfloat16* __restrict__ Ahi, const __nv_bfloat16* __restrict__ Alo,
             const __nv_bfloat16* __restrict__ Bhi, const __nv_bfloat16* __restrict__ Blo,
             const float* __restrict__ bias,
             float* __restrict__ Cf, __nv_bfloat16* __restrict__ Chi,
             __nv_bfloat16* __restrict__ Clo,
             int M, int N, int K, int splitout)
{
    extern __shared__ __nv_bfloat16 sm[];
    __nv_bfloat16* sAh = sm;
    __nv_bfloat16* sAl = sAh + 128 * 72;
    __nv_bfloat16* sBh = sAl + 128 * 72;
    __nv_bfloat16* sBl = sBh + 128 * 72;

    int t = threadIdx.x, lane = t & 31, w = t >> 5;
    int wm = w >> 1, wn = w & 1;
    int bm = blockIdx.y * 128, bn = blockIdx.x * 128;

    int arow = lane & 15, acolh = (lane >> 4) << 3;
    int bg = lane >> 3, bw8 = lane & 7;
    int brow = bw8 + ((bg >> 1) << 3), bcol = (bg & 1) << 3;

    u32 aBh = smem_u32(sAh), aBl = smem_u32(sAl);
    u32 bBh = smem_u32(sBh), bBl = smem_u32(sBl);

    float acc[2][8][4];
#pragma unroll
    for (int i = 0; i < 2; i++)
#pragma unroll
        for (int j = 0; j < 8; j++)
#pragma unroll
            for (int q = 0; q < 4; q++) acc[i][j][q] = 0.f;

    int NC = K >> 6;
    for (int c = 0; c < NC; c++) {
        __syncthreads();
#pragma unroll
        for (int j = 0; j < 4; j++) {
            int id = t + 256 * j;
            int row = id >> 3, ch = (id & 7) << 3;
            size_t ga = (size_t)(bm + row) * K + c * 64 + ch;
            *(uint4*)(sAh + row * 72 + ch) = *(const uint4*)(Ahi + ga);
            *(uint4*)(sAl + row * 72 + ch) = *(const uint4*)(Alo + ga);
            size_t gb = (size_t)(bn + row) * K + c * 64 + ch;
            *(uint4*)(sBh + row * 72 + ch) = *(const uint4*)(Bhi + gb);
            *(uint4*)(sBl + row * 72 + ch) = *(const uint4*)(Blo + gb);
        }
        __syncthreads();
#pragma unroll
        for (int ks = 0; ks < 4; ks++) {
            u32 ah[2][4], al[2][4];
#pragma unroll
            for (int mt = 0; mt < 2; mt++) {
                u32 off = (u32)(((wm * 32 + mt * 16 + arow) * 72 + ks * 16 + acolh) * 2);
                ldm_x4(ah[mt], aBh + off);
                ldm_x4(al[mt], aBl + off);
            }
#pragma unroll
            for (int np = 0; np < 4; np++) {
                u32 bh[4], bl[4];
                u32 off = (u32)(((wn * 64 + np * 16 + brow) * 72 + ks * 16 + bcol) * 2);
                ldm_x4(bh, bBh + off);
                ldm_x4(bl, bBl + off);
#pragma unroll
                for (int mt = 0; mt < 2; mt++) {
                    mma_bf16(acc[mt][2 * np],     ah[mt], bh[0], bh[1]);
                    mma_bf16(acc[mt][2 * np + 1], ah[mt], bh[2], bh[3]);
                    mma_bf16(acc[mt][2 * np],     al[mt], bh[0], bh[1]);
                    mma_bf16(acc[mt][2 * np + 1], al[mt], bh[2], bh[3]);
                    mma_bf16(acc[mt][2 * np],     ah[mt], bl[0], bl[1]);
                    mma_bf16(acc[mt][2 * np + 1], ah[mt], bl[2], bl[3]);
                }
            }
        }
    }

    int r = lane >> 2, cb = (lane & 3) * 2;
#pragma unroll
    for (int mt = 0; mt < 2; mt++) {
#pragma unroll
        for (int nt = 0; nt < 8; nt++) {
            int col = bn + wn * 64 + nt * 8 + cb;
            float2 bv = *(const float2*)(bias + col);
#pragma unroll
            for (int ri = 0; ri < 2; ri++) {
                int row = bm + wm * 32 + mt * 16 + r + ri * 8;
                float v0 = acc[mt][nt][ri * 2 + 0] + bv.x;
                float v1 = acc[mt][nt][ri * 2 + 1] + bv.y;
                if (splitout) {
                    __nv_bfloat162 hh, ll;
                    split_pair(v0, v1, hh, ll);
                    *(__nv_bfloat162*)(Chi + (size_t)row * N + col) = hh;
                    *(__nv_bfloat162*)(Clo + (size_t)row * N + col) = ll;
                } else {
                    float2 o; o.x = v0; o.y = v1;
                    *(float2*)(Cf + (size_t)row * N + col) = o;
                }
            }
        }
    }
}

// ---------------------------------------------------------------------------
// Flash attention via mma.sync bf16 3-term split.
// CTA: 128 q-rows x 1 head, 8 warps x 16 rows each, k-tiles of 128.
// smem: Q/K/V hi+lo [128][72] each, P hi+lo [128][136].
// ---------------------------------------------------------------------------
#define ATTN_SMEM ((6 * 128 * 72 + 2 * 128 * 136) * 2)

__global__ __launch_bounds__(256, 1)
void attn_mma(const __nv_bfloat16* __restrict__ qh_g, const __nv_bfloat16* __restrict__ ql_g,
              __nv_bfloat16* __restrict__ oh_g, __nv_bfloat16* __restrict__ ol_g)
{
    extern __shared__ __nv_bfloat16 sm[];
    __nv_bfloat16* Qh = sm;
    __nv_bfloat16* Ql = Qh + 128 * 72;
    __nv_bfloat16* Kh = Ql + 128 * 72;
    __nv_bfloat16* Kl = Kh + 128 * 72;
    __nv_bfloat16* Vh = Kl + 128 * 72;
    __nv_bfloat16* Vl = Vh + 128 * 72;
    __nv_bfloat16* Ph = Vl + 128 * 72;
    __nv_bfloat16* Pl = Ph + 128 * 136;

    int h = blockIdx.y;
    int q0 = blockIdx.x * 128;
    int t = threadIdx.x, lane = t & 31, w = t >> 5;

    // stage Q (scale 1/8 folded in — exact in bf16)
    {
        int row = t >> 1, half = t & 1;
        const __nv_bfloat16* gh = qh_g + (size_t)(q0 + row) * QKVN + h * 192 + half * 32;
        const __nv_bfloat16* gl = ql_g + (size_t)(q0 + row) * QKVN + h * 192 + half * 32;
        __nv_bfloat162 sc = __float2bfloat162_rn(0.125f);
#pragma unroll
        for (int j = 0; j < 4; j++) {
            uint4 vh4 = *(const uint4*)(gh + j * 8);
            uint4 vl4 = *(const uint4*)(gl + j * 8);
            __nv_bfloat162* p2h = (__nv_bfloat162*)&vh4;
            __nv_bfloat162* p2l = (__nv_bfloat162*)&vl4;
#pragma unroll
            for (int q = 0; q < 4; q++) {
                p2h[q] = __hmul2(p2h[q], sc);
                p2l[q] = __hmul2(p2l[q], sc);
            }
            *(uint4*)(Qh + row * 72 + half * 32 + j * 8) = vh4;
            *(uint4*)(Ql + row * 72 + half * 32 + j * 8) = vl4;
        }
    }
    __syncthreads();

    int arow = lane & 15, acolh = (lane >> 4) << 3;
    u32 qfh[4][4], qfl[4][4];
    {
        u32 qhb = smem_u32(Qh), qlb = smem_u32(Ql);
#pragma unroll
        for (int ks = 0; ks < 4; ks++) {
            u32 off = (u32)(((w * 16 + arow) * 72 + ks * 16 + acolh) * 2);
            ldm_x4(qfh[ks], qhb + off);
            ldm_x4(qfl[ks], qlb + off);
        }
    }

    int bg = lane >> 3, bw8 = lane & 7;
    int brow = bw8 + ((bg >> 1) << 3), bcol = (bg & 1) << 3;
    int vrow = bw8 + ((bg & 1) << 3), vcol = (bg >> 1) << 3;

    u32 khb = smem_u32(Kh), klb = smem_u32(Kl);
    u32 vhb = smem_u32(Vh), vlb = smem_u32(Vl);
    u32 phb = smem_u32(Ph), plb = smem_u32(Pl);

    float m0 = -1e30f, m1 = -1e30f, l0 = 0.f, l1 = 0.f;
    float oacc[8][4];
#pragma unroll
    for (int i = 0; i < 8; i++)
#pragma unroll
        for (int j = 0; j < 4; j++) oacc[i][j] = 0.f;

    for (int kt = 0; kt < SEQ; kt += 128) {
        __syncthreads();
        {
            int row = t >> 1, half = t & 1;
            size_t gb = (size_t)(kt + row) * QKVN + h * 192;
#pragma unroll
            for (int j = 0; j < 4; j++) {
                int co = half * 32 + j * 8;
                *(uint4*)(Kh + row * 72 + co) = *(const uint4*)(qh_g + gb + 64 + co);
                *(uint4*)(Kl + row * 72 + co) = *(const uint4*)(ql_g + gb + 64 + co);
                *(uint4*)(Vh + row * 72 + co) = *(const uint4*)(qh_g + gb + 128 + co);
                *(uint4*)(Vl + row * 72 + co) = *(const uint4*)(ql_g + gb + 128 + co);
            }
        }
        __syncthreads();

        float sacc[16][4];
#pragma unroll
        for (int i = 0; i < 16; i++)
#pragma unroll
            for (int j = 0; j < 4; j++) sacc[i][j] = 0.f;

#pragma unroll
        for (int ks = 0; ks < 4; ks++) {
#pragma unroll
            for (int np = 0; np < 8; np++) {
                u32 bh[4], bl[4];
                u32 off = (u32)(((np * 16 + brow) * 72 + ks * 16 + bcol) * 2);
                ldm_x4(bh, khb + off);
                ldm_x4(bl, klb + off);
                mma_bf16(sacc[2 * np],     qfh[ks], bh[0], bh[1]);
                mma_bf16(sacc[2 * np + 1], qfh[ks], bh[2], bh[3]);
                mma_bf16(sacc[2 * np],     qfl[ks], bh[0], bh[1]);
                mma_bf16(sacc[2 * np + 1], qfl[ks], bh[2], bh[3]);
                mma_bf16(sacc[2 * np],     qfh[ks], bl[0], bl[1]);
                mma_bf16(sacc[2 * np + 1], qfh[ks], bl[2], bl[3]);
            }
        }

        // online softmax (rows lane/4 and lane/4+8; 4 lanes per row)
        float mx0 = -1e30f, mx1 = -1e30f;
#pragma unroll
        for (int tl = 0; tl < 16; tl++) {
            mx0 = fmaxf(mx0, fmaxf(sacc[tl][0], sacc[tl][1]));
            mx1 = fmaxf(mx1, fmaxf(sacc[tl][2], sacc[tl][3]));
        }
        mx0 = fmaxf(mx0, __shfl_xor_sync(0xffffffffu, mx0, 1));
        mx0 = fmaxf(mx0, __shfl_xor_sync(0xffffffffu, mx0, 2));
        mx1 = fmaxf(mx1, __shfl_xor_sync(0xffffffffu, mx1, 1));
        mx1 = fmaxf(mx1, __shfl_xor_sync(0xffffffffu, mx1, 2));
        float mn0 = fmaxf(m0, mx0), mn1 = fmaxf(m1, mx1);
        float c0 = __expf(m0 - mn0), c1 = __expf(m1 - mn1);
        m0 = mn0; m1 = mn1;
#pragma unroll
        for (int d = 0; d < 8; d++) {
            oacc[d][0] *= c0; oacc[d][1] *= c0;
            oacc[d][2] *= c1; oacc[d][3] *= c1;
        }
        float s0 = 0.f, s1 = 0.f;
        int pr0 = w * 16 + (lane >> 2);
        int pc = (lane & 3) * 2;
#pragma unroll
        for (int tl = 0; tl < 16; tl++) {
            float p00 = __expf(sacc[tl][0] - mn0);
            float p01 = __expf(sacc[tl][1] - mn0);
            float p10 = __expf(sacc[tl][2] - mn1);
            float p11 = __expf(sacc[tl][3] - mn1);
            s0 += p00 + p01; s1 += p10 + p11;
            __nv_bfloat162 hh, ll;
            split_pair(p00, p01, hh, ll);
            *(__nv_bfloat162*)(Ph + pr0 * 136 + tl * 8 + pc) = hh;
            *(__nv_bfloat162*)(Pl + pr0 * 136 + tl * 8 + pc) = ll;
            split_pair(p10, p11, hh, ll);
            *(__nv_bfloat162*)(Ph + (pr0 + 8) * 136 + tl * 8 + pc) = hh;
            *(__nv_bfloat162*)(Pl + (pr0 + 8) * 136 + tl * 8 + pc) = ll;
        }
        s0 += __shfl_xor_sync(0xffffffffu, s0, 1);
        s0 += __shfl_xor_sync(0xffffffffu, s0, 2);
        s1 += __shfl_xor_sync(0xffffffffu, s1, 1);
        s1 += __shfl_xor_sync(0xffffffffu, s1, 2);
        l0 = l0 * c0 + s0;
        l1 = l1 * c1 + s1;
        __syncwarp();   // P rows are warp-private: warp-level sync suffices

        // PV: O += P @ V  (V as trans B-operand)
#pragma unroll
        for (int ks = 0; ks < 8; ks++) {
            u32 pfh[4], pfl[4];
            u32 poff = (u32)(((w * 16 + arow) * 136 + ks * 16 + acolh) * 2);
            ldm_x4(pfh, phb + poff);
            ldm_x4(pfl, plb + poff);
#pragma unroll
            for (int dp = 0; dp < 4; dp++) {
                u32 vh[4], vl[4];
                u32 voff = (u32)(((ks * 16 + vrow) * 72 + dp * 16 + vcol) * 2);
                ldm_x4_t(vh, vhb + voff);
                ldm_x4_t(vl, vlb + voff);
                mma_bf16(oacc[2 * dp],     pfh, vh[0], vh[1]);
                mma_bf16(oacc[2 * dp + 1], pfh, vh[2], vh[3]);
                mma_bf16(oacc[2 * dp],     pfl, vh[0], vh[1]);
                mma_bf16(oacc[2 * dp + 1], pfl, vh[2], vh[3]);
                mma_bf16(oacc[2 * dp],     pfh, vl[0], vl[1]);
                mma_bf16(oacc[2 * dp + 1], pfh, vl[2], vl[3]);
            }
        }
    }

    // epilogue: normalize, split to bf16 hi/lo for the out-projection
    float i0 = 1.f / l0, i1 = 1.f / l1;
    int orow = q0 + w * 16 + (lane >> 2);
    int cb2 = (lane & 3) * 2;
#pragma unroll
    for (int dt = 0; dt < 8; dt++) {
        int col = h * 64 + dt * 8 + cb2;
        __nv_bfloat162 hh, ll;
        split_pair(oacc[dt][0] * i0, oacc[dt][1] * i0, hh, ll);
        *(__nv_bfloat162*)(oh_g + (size_t)orow * EMB + col) = hh;
        *(__nv_bfloat162*)(ol_g + (size_t)orow * EMB + col) = ll;
        split_pair(oacc[dt][2] * i1, oacc[dt][3] * i1, hh, ll);
        *(__nv_bfloat162*)(oh_g + (size_t)(orow + 8) * EMB + col) = hh;
        *(__nv_bfloat162*)(ol_g + (size_t)(orow + 8) * EMB + col) = ll;
    }
}

extern "C" void kernel_launch(void* const* d_in, const int* in_sizes, int n_in,
                              void* d_out, int out_size)
{
    (void)in_sizes; (void)n_in; (void)out_size;
    const float* x    = (const float*)d_in[0];
    const float* Wqkv = (const float*)d_in[1];
    const float* bqkv = (const float*)d_in[2];
    const float* Wo   = (const float*)d_in[3];
    const float* bo   = (const float*)d_in[4];
    float* out = (float*)d_out;

    __nv_bfloat16 *xh, *xl, *wqh, *wql, *woh, *wol, *qkvh, *qkvl, *ath, *atl;
    cudaGetSymbolAddress((void**)&xh, g_x_hi);
    cudaGetSymbolAddress((void**)&xl, g_x_lo);
    cudaGetSymbolAddress((void**)&wqh, g_wqkv_hi);
    cudaGetSymbolAddress((void**)&wql, g_wqkv_lo);
    cudaGetSymbolAddress((void**)&woh, g_wo_hi);
    cudaGetSymbolAddress((void**)&wol, g_wo_lo);
    cudaGetSymbolAddress((void**)&qkvh, g_qkv_hi);
    cudaGetSymbolAddress((void**)&qkvl, g_qkv_lo);
    cudaGetSymbolAddress((void**)&ath, g_att_hi);
    cudaGetSymbolAddress((void**)&atl, g_att_lo);

    cudaFuncSetAttribute(lin_mma, cudaFuncAttributeMaxDynamicSharedMemorySize, LIN_SMEM);
    cudaFuncSetAttribute(attn_mma, cudaFuncAttributeMaxDynamicSharedMemorySize, ATTN_SMEM);

    // split fp32 inputs to bf16 hi/lo
    {
        int n4 = SEQ * EMB / 4;
        split_kernel<<<(n4 + 255) / 256, 256>>>(x, xh, xl, n4);
        n4 = QKVN * EMB / 4;
        split_kernel<<<(n4 + 255) / 256, 256>>>(Wqkv, wqh, wql, n4);
        n4 = EMB * EMB / 4;
        split_kernel<<<(n4 + 255) / 256, 256>>>(Wo, woh, wol, n4);
    }

    // 1) qkv = x @ Wqkv^T + bqkv  -> bf16 hi/lo directly
    dim3 g1(QKVN / 128, SEQ / 128);
    lin_mma<<<g1, 256, LIN_SMEM>>>(xh, xl, wqh, wql, bqkv,
                                   nullptr, qkvh, qkvl, SEQ, QKVN, EMB, 1);

    // 2) attention -> att bf16 hi/lo
    dim3 g2(SEQ / 128, NH);
    attn_mma<<<g2, 256, ATTN_SMEM>>>(qkvh, qkvl, ath, atl);

    // 3) out = att @ Wo^T + bo  -> f32
    dim3 g3(EMB / 128, SEQ / 128);
    lin_mma<<<g3, 256, LIN_SMEM>>>(ath, atl, woh, wol, bo,
                                   out, nullptr, nullptr, SEQ, EMB, EMB, 0);
}